// round 12
// baseline (speedup 1.0000x reference)
#include <cuda_runtime.h>
#include <cuda_bf16.h>

// Problem constants
#define T_DIM 1024
#define B_DIM 128
#define C_DIM 256
#define L_DIM 64
#define S_DIM 129           // 2*L+1
#define BC    (B_DIM * C_DIM)
#define NEGV  (-1e30f)
#define LOG2E 1.4426950408889634f
#define LN2   0.6931471805599453f

#define DGRP  8             // cp.async groups primed (1 row each)
#define NSLOT 10            // smem row ring slots
#define N_ENT_BLOCKS 1024
#define THREADS 256

// Deterministic two-stage reduction scratch (fully overwritten every call)
__device__ float g_ent_part[N_ENT_BLOCKS];
__device__ float g_ctc_part[B_DIM];

#define CP_ASYNC_16(dst_smem_u32, src_gptr) \
    asm volatile("cp.async.cg.shared.global [%0], [%1], 16;" :: "r"(dst_smem_u32), "l"(src_gptr))
#define CP_ASYNC_COMMIT() asm volatile("cp.async.commit_group;")
#define CP_ASYNC_WAIT(n)  asm volatile("cp.async.wait_group %0;" :: "n"(n))

__device__ __forceinline__ float ex2f(float x) {
    float r; asm("ex2.approx.f32 %0, %1;" : "=f"(r) : "f"(x)); return r;
}
__device__ __forceinline__ float lg2f(float x) {
    float r; asm("lg2.approx.f32 %0, %1;" : "=f"(r) : "f"(x)); return r;
}
// log2-domain logsumexp
__device__ __forceinline__ float lse2(float x, float y) {
    float m = fmaxf(x, y);
    return m + lg2f(ex2f(x - m) + ex2f(y - m));
}
__device__ __forceinline__ float lse3(float x, float y, float z) {
    float m = fmaxf(x, fmaxf(y, z));
    return m + lg2f(ex2f(x - m) + ex2f(y - m) + ex2f(z - m));
}

__global__ void __launch_bounds__(THREADS)
fused_ctc_entropy(const float* __restrict__ lp,
                  const int* __restrict__ targets,
                  const int* __restrict__ in_len,
                  const int* __restrict__ tgt_len)
{
    const int tid = threadIdx.x;

    if (blockIdx.x < B_DIM) {
        // ===== CTC DP: single warp, lane L owns states 4L..4L+3 (lane31 +128) =====
        if (tid >= 32) return;               // warps 1..7 idle in DP blocks
        const int L = tid;                   // lane id
        const int b = blockIdx.x;

        __shared__ float rows[NSLOT][C_DIM]; // staged RAW log_prob rows (10 KB)
        __shared__ float fin[132];           // final alphas for end capture

        const int* tg = targets + b * L_DIM;
        const int lab1 = tg[2 * L];          // label of state 4L+1 (j = 2L)
        const int lab3 = tg[2 * L + 1];      // label of state 4L+3 (j = 2L+1)
        const bool al1 = (L == 0) ? true : (lab1 != tg[2 * L - 1]);
        const bool al3 = (lab3 != lab1);

        const int Tlen = in_len[b];          // in [T/2, T]
        const int tl   = tgt_len[b];
        const float* rowbase = lp + b * C_DIM;

        // t = 0 init (log2 units). Only states 0,1 reachable (lane 0).
        float a0 = NEGV, a1 = NEGV, a2 = NEGV, a3 = NEGV, a4 = NEGV;
        if (L == 0) {
            a0 = rowbase[0]    * LOG2E;      // state 0 (blank)
            a1 = rowbase[lab1] * LOG2E;      // state 1
        }

        // Prime pipeline: rows 1..DGRP, one commit group per row (2x16B per lane)
        #pragma unroll
        for (int r = 1; r <= DGRP; ++r) {
            const float4* src = (const float4*)(rowbase + r * BC);
            unsigned d0 = (unsigned)__cvta_generic_to_shared(
                (float4*)rows[r % NSLOT] + L);
            unsigned d1 = (unsigned)__cvta_generic_to_shared(
                (float4*)rows[r % NSLOT] + L + 32);
            CP_ASYNC_16(d0, src + L);
            CP_ASYNC_16(d1, src + L + 32);
            CP_ASYNC_COMMIT();
        }

        // label probs for step 1 (row 1), log2 units
        CP_ASYNC_WAIT(7);                    // row 1 landed
        float prb = rows[1 % NSLOT][0]    * LOG2E;
        float g1  = rows[1 % NSLOT][lab1] * LOG2E;
        float g3  = rows[1 % NSLOT][lab3] * LOG2E;

        for (int t = 1; t < Tlen; ++t) {
            // neighbor halo: old a_{4L-1} = prev lane's a3
            float h1 = __shfl_up_sync(0xFFFFFFFFu, a3, 1);
            if (L == 0) h1 = NEGV;

            // states 4L..4L+3 (+128 on lane 31); even states: lse2 (no skip)
            float n0 = lse2(a0, h1)                      + prb;
            float n1 = lse3(a1, a0, al1 ? h1 : NEGV)     + g1;
            float n2 = lse2(a2, a1)                      + prb;
            float n3 = lse3(a3, a2, al3 ? a1 : NEGV)     + g3;
            if (L == 31) a4 = lse2(a4, a3) + prb;        // state 128
            a0 = n0; a1 = n1; a2 = n2; a3 = n3;

            // rows <= t+1 landed (warp-local wait, off the MUFU chain)
            CP_ASYNC_WAIT(6);

            // refill row t+DGRP (clamped)
            {
                int tpre = t + DGRP;
                if (tpre > T_DIM - 1) tpre = T_DIM - 1;
                const float4* src = (const float4*)(rowbase + tpre * BC);
                unsigned d0 = (unsigned)__cvta_generic_to_shared(
                    (float4*)rows[(t + DGRP) % NSLOT] + L);
                unsigned d1 = (unsigned)__cvta_generic_to_shared(
                    (float4*)rows[(t + DGRP) % NSLOT] + L + 32);
                CP_ASYNC_16(d0, src + L);
                CP_ASYNC_16(d1, src + L + 32);
                CP_ASYNC_COMMIT();
            }

            // prefetch next step's label probs (row t+1 resident)
            const float* rn = rows[(t + 1) % NSLOT];
            prb = rn[0]    * LOG2E;
            g1  = rn[lab1] * LOG2E;
            g3  = rn[lab3] * LOG2E;
        }
        CP_ASYNC_WAIT(0);                    // drain before exit

        // capture end states: alpha(log2) at t = Tlen-1
        fin[4 * L + 0] = a0;
        fin[4 * L + 1] = a1;
        fin[4 * L + 2] = a2;
        fin[4 * L + 3] = a3;
        if (L == 31) fin[128] = a4;
        __syncwarp();

        if (L == 0) {
            float e1 = fin[2 * tl];
            float e0 = fin[2 * tl - 1];
            float ll2v = lse2(e1, e0);
            float nll = -(ll2v * LN2);
            g_ctc_part[b] = (nll > 1e29f) ? 0.0f : nll;   // zero_infinity
        }
    } else {
        // ================= Entropy block: sum exp(lp)*lp =================
        __shared__ float red[THREADS / 32];
        const int eb = blockIdx.x - B_DIM;
        const float4* v = (const float4*)lp;
        const int n4 = (T_DIM * B_DIM * C_DIM) / 4;

        float acc = 0.0f;
        for (int i = eb * THREADS + tid; i < n4; i += N_ENT_BLOCKS * THREADS) {
            float4 x = v[i];
            acc += __expf(x.x) * x.x;
            acc += __expf(x.y) * x.y;
            acc += __expf(x.z) * x.z;
            acc += __expf(x.w) * x.w;
        }

        #pragma unroll
        for (int o = 16; o > 0; o >>= 1)
            acc += __shfl_down_sync(0xFFFFFFFFu, acc, o);
        if ((tid & 31) == 0) red[tid >> 5] = acc;
        __syncthreads();
        if (tid < THREADS / 32) {
            float r = red[tid];
            #pragma unroll
            for (int o = (THREADS / 64); o > 0; o >>= 1)
                r += __shfl_down_sync(0xFFFFFFFFu, r, o);
            if (tid == 0) g_ent_part[eb] = r;
        }
    }
}

__global__ void __launch_bounds__(256)
finalize_kernel(float* __restrict__ out)
{
    const int tid = threadIdx.x;
    float acc = 0.0f;
    for (int i = tid; i < N_ENT_BLOCKS; i += 256) acc += g_ent_part[i];

    float c = (tid < B_DIM) ? g_ctc_part[tid] : 0.0f;

    __shared__ float red[8], redc[8];
    #pragma unroll
    for (int o = 16; o > 0; o >>= 1) {
        acc += __shfl_down_sync(0xFFFFFFFFu, acc, o);
        c   += __shfl_down_sync(0xFFFFFFFFu, c, o);
    }
    if ((tid & 31) == 0) { red[tid >> 5] = acc; redc[tid >> 5] = c; }
    __syncthreads();
    if (tid == 0) {
        float es = 0.0f, cs = 0.0f;
        #pragma unroll
        for (int i = 0; i < 8; ++i) { es += red[i]; cs += redc[i]; }
        float smooth   = es / (float)(T_DIM * B_DIM);
        float ctc_mean = cs / (float)B_DIM;
        out[0] = 0.9f * ctc_mean + 0.1f * smooth;
    }
}

extern "C" void kernel_launch(void* const* d_in, const int* in_sizes, int n_in,
                              void* d_out, int out_size)
{
    const float* lp      = (const float*)d_in[0];
    const int*   targets = (const int*)d_in[1];
    const int*   in_len  = (const int*)d_in[2];
    const int*   tgt_len = (const int*)d_in[3];
    float*       out     = (float*)d_out;

    fused_ctc_entropy<<<B_DIM + N_ENT_BLOCKS, THREADS>>>(lp, targets, in_len, tgt_len);
    finalize_kernel<<<1, 256>>>(out);
}

// round 14
// speedup vs baseline: 2.6872x; 2.6872x over previous
#include <cuda_runtime.h>
#include <cuda_bf16.h>

// Problem constants
#define T_DIM 1024
#define B_DIM 128
#define C_DIM 256
#define L_DIM 64
#define S_DIM 129           // 2*L+1
#define BC    (B_DIM * C_DIM)
#define NEGV  (-1e30f)
#define LOG2E 1.4426950408889634f
#define LN2   0.6931471805599453f

#define NSLOT 12            // smem row ring slots (live window = 10)
#define N_ENT_BLOCKS 1024
#define THREADS 256

// Deterministic two-stage reduction scratch (fully overwritten every call)
__device__ float g_ent_part[N_ENT_BLOCKS];
__device__ float g_ctc_part[B_DIM];

#define CP_ASYNC_16(dst_smem_u32, src_gptr) \
    asm volatile("cp.async.cg.shared.global [%0], [%1], 16;" :: "r"(dst_smem_u32), "l"(src_gptr))
#define CP_ASYNC_COMMIT() asm volatile("cp.async.commit_group;")
#define CP_ASYNC_WAIT(n)  asm volatile("cp.async.wait_group %0;" :: "n"(n))

__device__ __forceinline__ float ex2f(float x) {
    float r; asm("ex2.approx.f32 %0, %1;" : "=f"(r) : "f"(x)); return r;
}
__device__ __forceinline__ float lg2f(float x) {
    float r; asm("lg2.approx.f32 %0, %1;" : "=f"(r) : "f"(x)); return r;
}

__global__ void __launch_bounds__(THREADS)
fused_ctc_entropy(const float* __restrict__ lp,
                  const int* __restrict__ targets,
                  const int* __restrict__ in_len,
                  const int* __restrict__ tgt_len)
{
    const int tid = threadIdx.x;

    __shared__ float rows[NSLOT][C_DIM];   // staged RAW log_prob rows (12 KB)
    __shared__ float buf[2][S_DIM + 2];    // [pad2 | states], double buffered
    __shared__ float cap[2];
    __shared__ float red[THREADS / 32];

    if (blockIdx.x < B_DIM) {
        // ========== CTC DP block (R4 skeleton, log2 + off-chain gather) ==========
        const int b = blockIdx.x;
        const int s = tid;                   // state index; active for s < S_DIM
        const bool dp = (s < S_DIM);

        if (tid < 2) { buf[0][tid] = NEGV; buf[1][tid] = NEGV; }  // pads

        const int* tg = targets + b * L_DIM;
        int  label  = 0;
        bool allow2 = false;
        if (dp && (s & 1)) {
            int j = s >> 1;
            label  = tg[j];
            allow2 = (j == 0) || (label != tg[j - 1]);
        }

        const int Tlen = in_len[b];          // in [T/2, T]
        const int tl   = tgt_len[b];
        const float* rowbase = lp + b * C_DIM;

        // t = 0 init (log2 units)
        float a = NEGV;
        if (s <= 1) a = rowbase[label] * LOG2E;

        // Prime pipeline: 9 rows in 8 commit groups (group0 = rows 1,2).
        // Refills use float4 by threads 0..63; all warps commit (empty ok).
        {
            if (tid < 64) {
                const float4* s1 = (const float4*)(rowbase + 1 * BC);
                const float4* s2 = (const float4*)(rowbase + 2 * BC);
                unsigned d1 = (unsigned)__cvta_generic_to_shared((float4*)rows[1] + tid);
                unsigned d2 = (unsigned)__cvta_generic_to_shared((float4*)rows[2] + tid);
                CP_ASYNC_16(d1, s1 + tid);
                CP_ASYNC_16(d2, s2 + tid);
            }
            CP_ASYNC_COMMIT();
            #pragma unroll
            for (int r = 3; r <= 9; ++r) {
                if (tid < 64) {
                    const float4* sr = (const float4*)(rowbase + r * BC);
                    unsigned dr = (unsigned)__cvta_generic_to_shared(
                        (float4*)rows[r % NSLOT] + tid);
                    CP_ASYNC_16(dr, sr + tid);
                }
                CP_ASYNC_COMMIT();
            }
        }

        CP_ASYNC_WAIT(7);                    // group0 (rows 1,2) landed
        __syncthreads();                     // pads + rows visible block-wide

        // prefetch step-1 label prob (log2 units), off critical path
        float pr = dp ? rows[1][label] * LOG2E : 0.0f;

        int p = 0;
        for (int t = 1; t < Tlen; ++t) {
            if (dp) buf[p][2 + s] = a;
            CP_ASYNC_WAIT(7);                // own groups: rows <= t+1 landed
            __syncthreads();                 // orders all warps' waits + STS

            // refill row t+9 (clamped) into its slot; all warps commit
            {
                int tpre = t + 9;
                if (tpre > T_DIM - 1) tpre = T_DIM - 1;
                if (tid < 64) {
                    const float4* sr = (const float4*)(rowbase + tpre * BC);
                    unsigned dr = (unsigned)__cvta_generic_to_shared(
                        (float4*)rows[(t + 9) % NSLOT] + tid);
                    CP_ASYNC_16(dr, sr + tid);
                }
                CP_ASYNC_COMMIT();
            }

            if (dp) {
                float p1 = buf[p][1 + s];        // alpha_{s-1}
                float p2 = allow2 ? buf[p][s] : NEGV;
                float m  = fmaxf(a, fmaxf(p1, p2));
                a = m + lg2f(ex2f(a - m) + ex2f(p1 - m) + ex2f(p2 - m)) + pr;

                // prefetch next step's label prob (row t+1 resident), off-chain
                pr = rows[(t + 1) % NSLOT][label] * LOG2E;
            }
            p ^= 1;
        }
        CP_ASYNC_WAIT(0);                    // drain before exit

        // a holds alpha (log2) at t = Tlen-1; capture end states
        if (s == 2 * tl)     cap[0] = a;
        if (s == 2 * tl - 1) cap[1] = a;
        __syncthreads();

        if (s == 0) {
            float a1 = cap[0], a0 = cap[1];
            float m  = fmaxf(a1, a0);
            float ll2v = m + lg2f(ex2f(a1 - m) + ex2f(a0 - m));
            float nll = -(ll2v * LN2);
            g_ctc_part[b] = (nll > 1e29f) ? 0.0f : nll;   // zero_infinity
        }
    } else {
        // ================= Entropy block: sum exp(lp)*lp =================
        const int eb = blockIdx.x - B_DIM;
        const float4* v = (const float4*)lp;
        const int n4 = (T_DIM * B_DIM * C_DIM) / 4;

        float acc = 0.0f;
        for (int i = eb * THREADS + tid; i < n4; i += N_ENT_BLOCKS * THREADS) {
            float4 x = v[i];
            acc += __expf(x.x) * x.x;
            acc += __expf(x.y) * x.y;
            acc += __expf(x.z) * x.z;
            acc += __expf(x.w) * x.w;
        }

        #pragma unroll
        for (int o = 16; o > 0; o >>= 1)
            acc += __shfl_down_sync(0xFFFFFFFFu, acc, o);
        if ((tid & 31) == 0) red[tid >> 5] = acc;
        __syncthreads();
        if (tid < THREADS / 32) {
            float r = red[tid];
            #pragma unroll
            for (int o = (THREADS / 64); o > 0; o >>= 1)
                r += __shfl_down_sync(0xFFFFFFFFu, r, o);
            if (tid == 0) g_ent_part[eb] = r;
        }
    }
}

__global__ void __launch_bounds__(256)
finalize_kernel(float* __restrict__ out)
{
    const int tid = threadIdx.x;
    float acc = 0.0f;
    for (int i = tid; i < N_ENT_BLOCKS; i += 256) acc += g_ent_part[i];

    float c = (tid < B_DIM) ? g_ctc_part[tid] : 0.0f;

    __shared__ float red[8], redc[8];
    #pragma unroll
    for (int o = 16; o > 0; o >>= 1) {
        acc += __shfl_down_sync(0xFFFFFFFFu, acc, o);
        c   += __shfl_down_sync(0xFFFFFFFFu, c, o);
    }
    if ((tid & 31) == 0) { red[tid >> 5] = acc; redc[tid >> 5] = c; }
    __syncthreads();
    if (tid == 0) {
        float es = 0.0f, cs = 0.0f;
        #pragma unroll
        for (int i = 0; i < 8; ++i) { es += red[i]; cs += redc[i]; }
        float smooth   = es / (float)(T_DIM * B_DIM);
        float ctc_mean = cs / (float)B_DIM;
        out[0] = 0.9f * ctc_mean + 0.1f * smooth;
    }
}

extern "C" void kernel_launch(void* const* d_in, const int* in_sizes, int n_in,
                              void* d_out, int out_size)
{
    const float* lp      = (const float*)d_in[0];
    const int*   targets = (const int*)d_in[1];
    const int*   in_len  = (const int*)d_in[2];
    const int*   tgt_len = (const int*)d_in[3];
    float*       out     = (float*)d_out;

    fused_ctc_entropy<<<B_DIM + N_ENT_BLOCKS, THREADS>>>(lp, targets, in_len, tgt_len);
    finalize_kernel<<<1, 256>>>(out);
}

// round 16
// speedup vs baseline: 3.2578x; 1.2123x over previous
#include <cuda_runtime.h>
#include <cuda_bf16.h>

// Problem constants
#define T_DIM 1024
#define B_DIM 128
#define C_DIM 256
#define L_DIM 64
#define S_DIM 129           // 2*L+1
#define BC    (B_DIM * C_DIM)
#define NEGV  (-1e30f)
#define LOG2E 1.4426950408889634f
#define LN2   0.6931471805599453f

#define NSLOT 12            // smem row ring slots (live window = 10)
#define N_ENT_BLOCKS 1024
#define THREADS 256

// Deterministic two-stage reduction scratch (fully overwritten every call)
__device__ float g_ent_part[N_ENT_BLOCKS];
__device__ float g_ctc_part[B_DIM];

#define CP_ASYNC_16(dst_smem_u32, src_gptr) \
    asm volatile("cp.async.cg.shared.global [%0], [%1], 16;" :: "r"(dst_smem_u32), "l"(src_gptr))
#define CP_ASYNC_COMMIT() asm volatile("cp.async.commit_group;")
#define CP_ASYNC_WAIT(n)  asm volatile("cp.async.wait_group %0;" :: "n"(n))

__device__ __forceinline__ float ex2f(float x) {
    float r; asm("ex2.approx.f32 %0, %1;" : "=f"(r) : "f"(x)); return r;
}
__device__ __forceinline__ float lg2f(float x) {
    float r; asm("lg2.approx.f32 %0, %1;" : "=f"(r) : "f"(x)); return r;
}

__global__ void __launch_bounds__(THREADS)
fused_ctc_entropy(const float* __restrict__ lp,
                  const int* __restrict__ targets,
                  const int* __restrict__ in_len,
                  const int* __restrict__ tgt_len)
{
    const int tid = threadIdx.x;

    __shared__ float rows[NSLOT][C_DIM];   // staged RAW log_prob rows (12 KB)
    __shared__ float buf[2][S_DIM + 2];    // [pad2 | states], double buffered
    __shared__ float cap[2];
    __shared__ float red[THREADS / 32];

    if (blockIdx.x < B_DIM) {
        // ===== CTC DP block: warp-specialized =====
        //   warps 0-4 (tid<160): DP compute (state s = tid, active s<129)
        //   warps 5-6 (tid 160-223): cp.async loaders
        //   warp 7: exits
        if (tid >= 224) return;

        const int b = blockIdx.x;
        const int Tlen = in_len[b];          // in [T/2, T]
        const float* rowbase = lp + b * C_DIM;

        if (tid >= 160) {
            // ---------------- loader warps ----------------
            const int lt = tid - 160;        // 0..63, one float4 per thread
            // Prime: 9 rows in 8 commit groups (group0 = rows 1,2)
            {
                const float4* s1 = (const float4*)(rowbase + 1 * BC);
                const float4* s2 = (const float4*)(rowbase + 2 * BC);
                unsigned d1 = (unsigned)__cvta_generic_to_shared((float4*)rows[1] + lt);
                unsigned d2 = (unsigned)__cvta_generic_to_shared((float4*)rows[2] + lt);
                CP_ASYNC_16(d1, s1 + lt);
                CP_ASYNC_16(d2, s2 + lt);
                CP_ASYNC_COMMIT();
                #pragma unroll
                for (int r = 3; r <= 9; ++r) {
                    const float4* sr = (const float4*)(rowbase + r * BC);
                    unsigned dr = (unsigned)__cvta_generic_to_shared(
                        (float4*)rows[r % NSLOT] + lt);
                    CP_ASYNC_16(dr, sr + lt);
                    CP_ASYNC_COMMIT();
                }
            }
            CP_ASYNC_WAIT(7);                // rows 1,2 landed
            __syncthreads();                 // matches compute warps' pre-loop sync

            for (int t = 1; t < Tlen; ++t) {
                CP_ASYNC_WAIT(7);            // rows <= t+1 landed
                __syncthreads();             // per-step barrier (data now visible)
                int tpre = t + 9;
                if (tpre > T_DIM - 1) tpre = T_DIM - 1;
                const float4* sr = (const float4*)(rowbase + tpre * BC);
                unsigned dr = (unsigned)__cvta_generic_to_shared(
                    (float4*)rows[(t + 9) % NSLOT] + lt);
                CP_ASYNC_16(dr, sr + lt);
                CP_ASYNC_COMMIT();
            }
            CP_ASYNC_WAIT(0);                // drain; then exit (no more barriers)
            return;
        }

        // ---------------- DP compute warps (tid < 160) ----------------
        const int s = tid;                   // state index; active for s < S_DIM
        const bool dp = (s < S_DIM);

        if (tid < 2) { buf[0][tid] = NEGV; buf[1][tid] = NEGV; }  // pads

        const int* tg = targets + b * L_DIM;
        int  label  = 0;
        bool allow2 = false;
        if (dp && (s & 1)) {
            int j = s >> 1;
            label  = tg[j];
            allow2 = (j == 0) || (label != tg[j - 1]);
        }
        const int tl = tgt_len[b];

        // t = 0 init (log2 units)
        float a = NEGV;
        if (s <= 1) a = rowbase[label] * LOG2E;

        __syncthreads();                     // pads + rows 1,2 visible

        // step-1 label prob (log2), off critical path
        float pr = dp ? rows[1][label] * LOG2E : 0.0f;

        int p = 0;
        for (int t = 1; t < Tlen; ++t) {
            if (dp) buf[p][2 + s] = a;
            __syncthreads();                 // loaders guaranteed rows <= t+1 landed

            if (dp) {
                float p1 = buf[p][1 + s];        // alpha_{s-1}
                float p2 = allow2 ? buf[p][s] : NEGV;
                float m  = fmaxf(a, fmaxf(p1, p2));
                a = m + lg2f(ex2f(a - m) + ex2f(p1 - m) + ex2f(p2 - m)) + pr;

                // prefetch next step's label prob (row t+1 resident), off-chain
                pr = rows[(t + 1) % NSLOT][label] * LOG2E;
            }
            p ^= 1;
        }

        // a holds alpha (log2) at t = Tlen-1; capture end states
        if (s == 2 * tl)     cap[0] = a;
        if (s == 2 * tl - 1) cap[1] = a;
        __syncthreads();                     // loaders already exited; counts live warps

        if (s == 0) {
            float a1 = cap[0], a0 = cap[1];
            float m  = fmaxf(a1, a0);
            float ll2v = m + lg2f(ex2f(a1 - m) + ex2f(a0 - m));
            float nll = -(ll2v * LN2);
            g_ctc_part[b] = (nll > 1e29f) ? 0.0f : nll;   // zero_infinity
        }
    } else {
        // ================= Entropy block: sum exp(lp)*lp =================
        const int eb = blockIdx.x - B_DIM;
        const float4* v = (const float4*)lp;
        const int n4 = (T_DIM * B_DIM * C_DIM) / 4;

        float acc = 0.0f;
        for (int i = eb * THREADS + tid; i < n4; i += N_ENT_BLOCKS * THREADS) {
            float4 x = v[i];
            acc += __expf(x.x) * x.x;
            acc += __expf(x.y) * x.y;
            acc += __expf(x.z) * x.z;
            acc += __expf(x.w) * x.w;
        }

        #pragma unroll
        for (int o = 16; o > 0; o >>= 1)
            acc += __shfl_down_sync(0xFFFFFFFFu, acc, o);
        if ((tid & 31) == 0) red[tid >> 5] = acc;
        __syncthreads();
        if (tid < THREADS / 32) {
            float r = red[tid];
            #pragma unroll
            for (int o = (THREADS / 64); o > 0; o >>= 1)
                r += __shfl_down_sync(0xFFFFFFFFu, r, o);
            if (tid == 0) g_ent_part[eb] = r;
        }
    }
}

__global__ void __launch_bounds__(256)
finalize_kernel(float* __restrict__ out)
{
    const int tid = threadIdx.x;
    float acc = 0.0f;
    for (int i = tid; i < N_ENT_BLOCKS; i += 256) acc += g_ent_part[i];

    float c = (tid < B_DIM) ? g_ctc_part[tid] : 0.0f;

    __shared__ float red[8], redc[8];
    #pragma unroll
    for (int o = 16; o > 0; o >>= 1) {
        acc += __shfl_down_sync(0xFFFFFFFFu, acc, o);
        c   += __shfl_down_sync(0xFFFFFFFFu, c, o);
    }
    if ((tid & 31) == 0) { red[tid >> 5] = acc; redc[tid >> 5] = c; }
    __syncthreads();
    if (tid == 0) {
        float es = 0.0f, cs = 0.0f;
        #pragma unroll
        for (int i = 0; i < 8; ++i) { es += red[i]; cs += redc[i]; }
        float smooth   = es / (float)(T_DIM * B_DIM);
        float ctc_mean = cs / (float)B_DIM;
        out[0] = 0.9f * ctc_mean + 0.1f * smooth;
    }
}

extern "C" void kernel_launch(void* const* d_in, const int* in_sizes, int n_in,
                              void* d_out, int out_size)
{
    const float* lp      = (const float*)d_in[0];
    const int*   targets = (const int*)d_in[1];
    const int*   in_len  = (const int*)d_in[2];
    const int*   tgt_len = (const int*)d_in[3];
    float*       out     = (float*)d_out;

    fused_ctc_entropy<<<B_DIM + N_ENT_BLOCKS, THREADS>>>(lp, targets, in_len, tgt_len);
    finalize_kernel<<<1, 256>>>(out);
}